// round 8
// baseline (speedup 1.0000x reference)
#include <cuda_runtime.h>

#define LSEQ    2048
#define NBATCH  32
#define TPB     256
#define NBLOCKS 444          // 3 * 148: exactly 3 resident blocks per SM
#define PAIRS_PER_UNIT 16
#define CHUNKS_PER_BATCH 64  // 1024 pairs / 16
#define NUNITS  (NBATCH * CHUNKS_PER_BATCH)   // 2048
#define SPLIT   16           // key-split ways per query pair
#define DTC     0.01f

// log2(e)/sqrt(3): folds softmax scale + e^x->2^x into q
#define QSCALE (1.4426950408889634f / 1.7320508075688772f)

__device__ unsigned g_unit_counter;

__global__ void reset_counter_kernel() { g_unit_counter = 0u; }

__device__ __forceinline__ float ex2(float x) {
    float r;
    asm("ex2.approx.f32 %0, %1;" : "=f"(r) : "f"(x));
    return r;
}

#define PACK2(d, lo, hi)   asm("mov.b64 %0, {%1, %2};" : "=l"(d) : "f"(lo), "f"(hi))
#define UNPACK2(lo, hi, d) asm("mov.b64 {%0, %1}, %2;" : "=f"(lo), "=f"(hi) : "l"(d))
#define FMA2(d, a, b, c)   asm("fma.rn.f32x2 %0, %1, %2, %3;" : "=l"(d) : "l"(a), "l"(b), "l"(c))

// Softmax partials for one query over this lane's strided key subset.
// kv[2j] = {k0,k1,k2,0}, kv[2j+1] = {v0,v1,v2,1.0}
// acc01 = packed {a0,a1}, acc2d = packed {a2, den}
__device__ __forceinline__ void accum_query(
    const float4* __restrict__ kv, int len, int s,
    float q0, float q1, float q2,
    float& a0, float& a1, float& a2, float& den)
{
    unsigned long long acc01 = 0ull, acc2d = 0ull;
    #pragma unroll 4
    for (int j = s; j < len; j += SPLIT) {
        float4 K = kv[2 * j];
        float4 V = kv[2 * j + 1];
        float sc = fmaf(K.z, q2, fmaf(K.y, q1, K.x * q0));
        float w  = ex2(sc);
        unsigned long long wp, vp01, vp2d;
        PACK2(wp, w, w);
        PACK2(vp01, V.x, V.y);
        PACK2(vp2d, V.z, V.w);
        FMA2(acc01, wp, vp01, acc01);
        FMA2(acc2d, wp, vp2d, acc2d);
    }
    UNPACK2(a0, a1, acc01);
    UNPACK2(a2, den, acc2d);
}

__global__ void __launch_bounds__(TPB, 3) ac_kernel(
    const float* __restrict__ inputs,
    const float* __restrict__ wi,  const float* __restrict__ bi,
    const float* __restrict__ wo,  const float* __restrict__ bo,
    const float* __restrict__ f1w, const float* __restrict__ f1b,
    const float* __restrict__ f2w, const float* __restrict__ f2b,
    const float* __restrict__ g1w, const float* __restrict__ g1b,
    const float* __restrict__ g2w, const float* __restrict__ g2b,
    const float* __restrict__ m1s, const float* __restrict__ m2s,
    const float* __restrict__ sigma,
    float* __restrict__ out)
{
    extern __shared__ float4 kv[];   // [2*LSEQ]: kv[2j]={k0,k1,k2,0}, kv[2j+1]={v0,v1,v2,1}
    __shared__ unsigned s_unit;

    const int t = threadIdx.x;

    const float scl0 = sigma[0] + 1e-5f;
    const float scl1 = sigma[1] + 1e-5f;
    const float inv0 = 1.0f / scl0;
    const float inv1 = 1.0f / scl1;

    const int  pr   = t >> 4;     // pair slot in unit (0..15)
    const int  s    = t & (SPLIT - 1);
    const unsigned full = 0xffffffffu;

    int prev_batch = -1;
    const float* xb = inputs;     // set per batch

    for (;;) {
        if (t == 0) s_unit = atomicAdd(&g_unit_counter, 1u);
        __syncthreads();                       // (A) also guards prior-unit KV reads
        const unsigned u = s_unit;
        if (u >= NUNITS) return;

        const int batch = (int)(u >> 6);       // u / CHUNKS_PER_BATCH
        const int chunk = (int)(u & 63u);

        if (batch != prev_batch) {
            xb = inputs + (size_t)batch * LSEQ * 3;
            // ---- build KV tile for this batch ----
            float wk[9], wv[9], bk[3], bv[3];
            #pragma unroll
            for (int i = 0; i < 9; i++) { wk[i] = wi[9 + i]; wv[i] = wi[18 + i]; }
            #pragma unroll
            for (int i = 0; i < 3; i++) { bk[i] = bi[3 + i]; bv[i] = bi[6 + i]; }
            #pragma unroll
            for (int r = t; r < LSEQ; r += TPB) {
                float x0 = xb[3 * r + 0];
                float x1 = xb[3 * r + 1] * inv0;
                float x2 = xb[3 * r + 2] * inv1;
                float k0 = bk[0] + wk[0] * x0 + wk[1] * x1 + wk[2] * x2;
                float k1 = bk[1] + wk[3] * x0 + wk[4] * x1 + wk[5] * x2;
                float k2 = bk[2] + wk[6] * x0 + wk[7] * x1 + wk[8] * x2;
                float v0 = bv[0] + wv[0] * x0 + wv[1] * x1 + wv[2] * x2;
                float v1 = bv[1] + wv[3] * x0 + wv[4] * x1 + wv[5] * x2;
                float v2 = bv[2] + wv[6] * x0 + wv[7] * x1 + wv[8] * x2;
                kv[2 * r + 0] = make_float4(k0, k1, k2, 0.0f);
                kv[2 * r + 1] = make_float4(v0, v1, v2, 1.0f);
            }
            __syncthreads();                   // (B) KV visible
            prev_batch = batch;
        }

        // ---- process unit: 16 pairs (p, 2047-p), 16 lanes split keys per pair ----
        const int p  = chunk * PAIRS_PER_UNIT + pr;   // 0..1023
        const int ia = p;
        const int ib = LSEQ - 1 - p;
        const int lenA = ia + 1;
        const int lenB = ib + 1;

        // q projections for both queries
        float qa0, qa1, qa2, qb0, qb1, qb2;
        {
            float wq[9], bq[3];
            #pragma unroll
            for (int i = 0; i < 9; i++) wq[i] = wi[i];
            #pragma unroll
            for (int i = 0; i < 3; i++) bq[i] = bi[i];

            float x0 = xb[3 * ia + 0];
            float x1 = xb[3 * ia + 1] * inv0;
            float x2 = xb[3 * ia + 2] * inv1;
            qa0 = (bq[0] + wq[0] * x0 + wq[1] * x1 + wq[2] * x2) * QSCALE;
            qa1 = (bq[1] + wq[3] * x0 + wq[4] * x1 + wq[5] * x2) * QSCALE;
            qa2 = (bq[2] + wq[6] * x0 + wq[7] * x1 + wq[8] * x2) * QSCALE;

            float y0 = xb[3 * ib + 0];
            float y1 = xb[3 * ib + 1] * inv0;
            float y2 = xb[3 * ib + 2] * inv1;
            qb0 = (bq[0] + wq[0] * y0 + wq[1] * y1 + wq[2] * y2) * QSCALE;
            qb1 = (bq[1] + wq[3] * y0 + wq[4] * y1 + wq[5] * y2) * QSCALE;
            qb2 = (bq[2] + wq[6] * y0 + wq[7] * y1 + wq[8] * y2) * QSCALE;
        }

        float a0, a1, a2, ad, c0, c1, c2, cd;
        accum_query(kv, lenA, s, qa0, qa1, qa2, a0, a1, a2, ad);
        accum_query(kv, lenB, s, qb0, qb1, qb2, c0, c1, c2, cd);

        // combine 16 split-lanes (butterfly within each 16-lane group)
        #pragma unroll
        for (int d = 1; d < SPLIT; d <<= 1) {
            a0 += __shfl_xor_sync(full, a0, d);
            a1 += __shfl_xor_sync(full, a1, d);
            a2 += __shfl_xor_sync(full, a2, d);
            ad += __shfl_xor_sync(full, ad, d);
            c0 += __shfl_xor_sync(full, c0, d);
            c1 += __shfl_xor_sync(full, c1, d);
            c2 += __shfl_xor_sync(full, c2, d);
            cd += __shfl_xor_sync(full, cd, d);
        }

        // lanes s==0 / s==1 finish queries a / b
        if (s < 2) {
            const float den = s ? cd : ad;
            const float r   = 1.0f / den;
            const float x0  = (s ? c0 : a0) * r;
            const float x1  = (s ? c1 : a1) * r;
            const float x2  = (s ? c2 : a2) * r;
            const int   i   = s ? ib : ia;

            float wo10 = wo[3], wo11 = wo[4], wo12 = wo[5];
            float wo20 = wo[6], wo21 = wo[7], wo22 = wo[8];
            float bo1 = bo[1], bo2 = bo[2];
            float G10 = g1w[0], G11 = g1w[1], G12 = g1w[2], G1B = g1b[0];
            float G20 = g2w[0], G21 = g2w[1], G22 = g2w[2], G2B = g2b[0];
            float F10 = f1w[0], F11 = f1w[1], F12 = f1w[2], F1B = f1b[0];
            float F20 = f2w[0], F21 = f2w[1], F22 = f2w[2], F2B = f2b[0];
            float M1 = m1s[0], M2 = m2s[0];

            float s1 = bo1 + wo10 * x0 + wo11 * x1 + wo12 * x2;
            float s2 = bo2 + wo20 * x0 + wo21 * x1 + wo22 * x2;

            float o[8];
            {
                float d1 = (G10 + G11 * s1 + G12 * s2 + G1B) * M1;
                float d2 = (G20 + G21 * s1 + G22 * s2 + G2B) * M2;
                s1 += DTC * d1; s2 += DTC * d2;
                o[0] = s1 * scl0; o[1] = s2 * scl1;
            }
            {
                float d1 = (G10 + G11 * s1 + G12 * s2 + G1B) * M1;
                float d2 = (G20 + G21 * s1 + G22 * s2 + G2B) * M2;
                s1 += DTC * d1; s2 += DTC * d2;
                o[2] = s1 * scl0; o[3] = s2 * scl1;
            }
            {
                float d1 = (G10 + G11 * s1 + G12 * s2 + G1B) * M1;
                float d2 = (G20 + G21 * s1 + G22 * s2 + G2B) * M2;
                s1 += DTC * d1; s2 += DTC * d2;
                o[4] = s1 * scl0; o[5] = s2 * scl1;
            }
            {
                float v1 = (F10 + F11 * s1 + F12 * s2 + F1B) * M1;
                float v2 = (F20 + F21 * s1 + F22 * s2 + F2B) * M2;
                o[6] = (s1 + v1 * DTC) * scl0;
                o[7] = (s2 + v2 * DTC) * scl1;
            }

            float4* op = reinterpret_cast<float4*>(out) + ((size_t)(batch * LSEQ + i)) * 2;
            op[0] = make_float4(o[0], o[1], o[2], o[3]);
            op[1] = make_float4(o[4], o[5], o[6], o[7]);
        }
        // next unit; loop-top __syncthreads guards KV until all lanes done
    }
}

extern "C" void kernel_launch(void* const* d_in, const int* in_sizes, int n_in,
                              void* d_out, int out_size)
{
    const float* inputs = (const float*)d_in[1];
    const float* wi     = (const float*)d_in[2];
    const float* bi     = (const float*)d_in[3];
    const float* wo     = (const float*)d_in[4];
    const float* bo     = (const float*)d_in[5];
    const float* f1w    = (const float*)d_in[6];
    const float* f1b    = (const float*)d_in[7];
    const float* f2w    = (const float*)d_in[8];
    const float* f2b    = (const float*)d_in[9];
    const float* g1w    = (const float*)d_in[10];
    const float* g1b    = (const float*)d_in[11];
    const float* g2w    = (const float*)d_in[12];
    const float* g2b    = (const float*)d_in[13];
    const float* m1s    = (const float*)d_in[14];
    const float* m2s    = (const float*)d_in[15];
    const float* sigma  = (const float*)d_in[16];
    float* out = (float*)d_out;

    const int smem = 2 * LSEQ * (int)sizeof(float4);   // 64 KB
    cudaFuncSetAttribute(ac_kernel, cudaFuncAttributeMaxDynamicSharedMemorySize, smem);

    reset_counter_kernel<<<1, 1>>>();
    ac_kernel<<<NBLOCKS, TPB, smem>>>(inputs, wi, bi, wo, bo,
                                      f1w, f1b, f2w, f2b,
                                      g1w, g1b, g2w, g2b,
                                      m1s, m2s, sigma, out);
}